// round 2
// baseline (speedup 1.0000x reference)
#include <cuda_runtime.h>

#define TT 20
#define MM 6
#define DD 9
#define NODES (TT*MM)      // 120
#define NTHREADS 192
#define STRIDE_MSG 13      // odd stride: conflict-free scatter
#define STRIDE_OUT 19      // odd stride: conflict-free scatter

// ---------------- FMA-only activations (no MUFU) ----------------

// e^{-a} for a >= 0 (clamped). FMA/ALU pipes only. deg-4 poly, err ~4e-5 rel.
__device__ __forceinline__ float fexpneg(float a) {
    a = fminf(a, 80.0f);
    float t = a * 1.4426950408889634f;       // t in [0, ~115.4]
    float z = t + 12582912.0f;               // round-to-nearest via 1.5*2^23
    int   n = __float_as_int(z) - 0x4B400000;
    float fn = z - 12582912.0f;
    float u = fn - t;                        // u in [-0.5, 0.5]; 2^{-t} = 2^{-n} * 2^{u}
    float p = 9.6181291076e-3f;
    p = fmaf(p, u, 5.5504108664e-2f);
    p = fmaf(p, u, 2.4022650696e-1f);
    p = fmaf(p, u, 6.9314718056e-1f);
    p = fmaf(p, u, 1.0f);
    return __int_as_float((127 - n) << 23) * p;
}

// 1/y for y in [1,2], 2 Newton iterations (err ~3.4e-6)
__device__ __forceinline__ float recip1to2(float y) {
    float r = fmaf(-0.5f, y, 1.45710678f);
    r = r * fmaf(-y, r, 2.0f);
    r = r * fmaf(-y, r, 2.0f);
    return r;
}

__device__ __forceinline__ float fsigmoid(float x) {
    float e = fexpneg(fabsf(x));
    float r = recip1to2(1.0f + e);           // sigmoid(|x|)
    return (x >= 0.0f) ? r : (1.0f - r);
}

__device__ __forceinline__ float ftanh_(float x) {
    float e = fexpneg(2.0f * fabsf(x));
    float r = recip1to2(1.0f + e);
    float th = fmaf(2.0f, r, -1.0f);         // tanh(|x|)
    return (x >= 0.0f) ? th : -th;
}

// ---------------- dot helpers ----------------

// smem weight row (16B aligned, stride 12) vs register vector
__device__ __forceinline__ float dot9(const float* __restrict__ w, const float* r) {
    float4 a = *(const float4*)w;
    float4 b = *(const float4*)(w + 4);
    float acc = w[8] * r[8];
    acc = fmaf(a.x, r[0], acc); acc = fmaf(a.y, r[1], acc);
    acc = fmaf(a.z, r[2], acc); acc = fmaf(a.w, r[3], acc);
    acc = fmaf(b.x, r[4], acc); acc = fmaf(b.y, r[5], acc);
    acc = fmaf(b.z, r[6], acc); acc = fmaf(b.w, r[7], acc);
    return acc;
}

// pure register-register dot
__device__ __forceinline__ float dot9r(const float* a, const float* b) {
    float acc = a[0] * b[0];
    #pragma unroll
    for (int j = 1; j < 9; j++) acc = fmaf(a[j], b[j], acc);
    return acc;
}

__device__ __forceinline__ void load9(float* r, const float* __restrict__ p) {
    float4 a = *(const float4*)p;
    float4 b = *(const float4*)(p + 4);
    r[0]=a.x; r[1]=a.y; r[2]=a.z; r[3]=a.w;
    r[4]=b.x; r[5]=b.y; r[6]=b.z; r[7]=b.w;
    r[8]=p[8];
}

// ---------------- fused kernel: one CTA per graph n ----------------

__global__ __launch_bounds__(NTHREADS, 1)
void gnn_lstm_kernel(
    const float* __restrict__ nf,   const float* __restrict__ pos,  const float* __restrict__ attm,
    const float* __restrict__ msgW, const float* __restrict__ msgb,
    const float* __restrict__ gWih, const float* __restrict__ gWhh,
    const float* __restrict__ gbih, const float* __restrict__ gbhh,
    const float* __restrict__ ro1W, const float* __restrict__ ro1b,
    const float* __restrict__ ro2W, const float* __restrict__ ro2b,
    const float* __restrict__ lfWih, const float* __restrict__ lfWhh,
    const float* __restrict__ lfbih, const float* __restrict__ lfbhh,
    const float* __restrict__ lbWih, const float* __restrict__ lbWhh,
    const float* __restrict__ lbbih, const float* __restrict__ lbbhh,
    const float* __restrict__ lr1W, const float* __restrict__ lr1b,
    const float* __restrict__ lr2W, const float* __restrict__ lr2b,
    const int* __restrict__ numrec,
    float* __restrict__ out_p, float* __restrict__ out_p0)
{
    // weights, rows padded to 12 (or 20) floats for aligned LDS.128
    __shared__ __align__(16) float s_msgW[9*12];
    __shared__ __align__(16) float s_msgb[12];
    __shared__ __align__(16) float s_gWih[27*12];
    __shared__ __align__(16) float s_gWhh[27*12];
    __shared__ __align__(16) float s_gbih[28];
    __shared__ __align__(16) float s_gbhh[28];
    __shared__ __align__(16) float s_ro1W[9*12];
    __shared__ __align__(16) float s_ro1b[12];
    __shared__ __align__(16) float s_ro2W[7*12];
    __shared__ __align__(16) float s_ro2b[8];
    __shared__ __align__(16) float s_lWih[2][36*12];
    __shared__ __align__(16) float s_lWhh[2][36*12];
    __shared__ __align__(16) float s_lb[2][40];      // bih + bhh combined
    __shared__ __align__(16) float s_lr1W[9*20];     // rows of 18, stride 20
    __shared__ __align__(16) float s_lr1b[12];
    __shared__ __align__(16) float s_lr2W[7*12];
    __shared__ __align__(16) float s_lr2b[8];
    // data
    __shared__ __align__(16) float s_x[NODES*12];    // node features -> GRU hidden (stride 12)
    __shared__ __align__(16) float s_buf[NODES*STRIDE_OUT];  // GRU msg (stride 13) / LSTM out (stride 19)
    __shared__ __align__(16) float s_att[NODES*8];   // masked att rows (stride 8)

    const int tid = threadIdx.x;
    const int n   = blockIdx.x;

    // ---- cooperative weight staging (pad rows) ----
    auto ldp = [&](float* dst, const float* src, int rows, int cols, int stride) {
        for (int i = tid; i < rows*cols; i += NTHREADS)
            dst[(i/cols)*stride + (i%cols)] = src[i];
    };
    ldp(s_msgW, msgW, 9, 9, 12);
    ldp(s_gWih, gWih, 27, 9, 12);
    ldp(s_gWhh, gWhh, 27, 9, 12);
    ldp(s_ro1W, ro1W, 9, 9, 12);
    ldp(s_ro2W, ro2W, 7, 9, 12);
    ldp(s_lWih[0], lfWih, 36, 9, 12);
    ldp(s_lWhh[0], lfWhh, 36, 9, 12);
    ldp(s_lWih[1], lbWih, 36, 9, 12);
    ldp(s_lWhh[1], lbWhh, 36, 9, 12);
    ldp(s_lr1W, lr1W, 9, 18, 20);
    ldp(s_lr2W, lr2W, 7, 9, 12);
    if (tid < 9)  s_msgb[tid] = msgb[tid];
    if (tid < 27) { s_gbih[tid] = gbih[tid]; s_gbhh[tid] = gbhh[tid]; }
    if (tid < 9)  s_ro1b[tid] = ro1b[tid];
    if (tid < 7)  s_ro2b[tid] = ro2b[tid];
    if (tid < 36) { s_lb[0][tid] = lfbih[tid] + lfbhh[tid];
                    s_lb[1][tid] = lbbih[tid] + lbbhh[tid]; }
    if (tid < 9)  s_lr1b[tid] = lr1b[tid];
    if (tid < 7)  s_lr2b[tid] = lr2b[tid];

    // mask depends only on num_rec[n, 0] (reference uses num_rec[:, 0:1])
    const int nr0 = numrec[(size_t)n * TT];

    // ---- stage node features (concat) + masked attention ----
    for (int i = tid; i < NODES*3; i += NTHREADS)
        s_x[(i/3)*12 + (i%3)] = nf[(size_t)n * NODES * 3 + i];
    for (int i = tid; i < NODES*6; i += NTHREADS)
        s_x[(i/6)*12 + 3 + (i%6)] = pos[(size_t)n * NODES * 6 + i];
    for (int i = tid; i < NODES*6; i += NTHREADS) {
        int c = i % 6;
        float v = attm[(size_t)n * NODES * 6 + i];
        s_att[(i/6)*8 + c] = (c < nr0) ? v : 0.0f;
    }
    __syncthreads();

    // ================= GRU message passing (thread = node (t,m)) =================
    const bool act = tid < NODES;
    const int t = tid / MM, m = tid % MM;
    float h[9];
    float attr[6];
    float vm = 0.0f;
    if (act) {
        #pragma unroll
        for (int d = 0; d < 9; d++) h[d] = s_x[tid*12 + d];
        #pragma unroll
        for (int j = 0; j < 6; j++) attr[j] = s_att[tid*8 + j];
        vm = (m < nr0) ? 1.0f : 0.0f;
    }

    #pragma unroll
    for (int rd = 0; rd < 2; rd++) {
        if (act) {
            #pragma unroll
            for (int g = 0; g < 9; g++)
                s_buf[tid*STRIDE_MSG + g] = s_msgb[g] + dot9(s_msgW + g*12, h);
        }
        __syncthreads();
        if (act) {
            float mg[9];
            #pragma unroll
            for (int d = 0; d < 9; d++) mg[d] = 0.0f;
            #pragma unroll
            for (int j = 0; j < 6; j++) {
                const float* mp = s_buf + (t*6 + j)*STRIDE_MSG;
                float aj = attr[j];
                #pragma unroll
                for (int d = 0; d < 9; d++) mg[d] = fmaf(aj, mp[d], mg[d]);
            }
            float hn[9];
            #pragma unroll
            for (int d = 0; d < 9; d++) {
                float a0  = s_gbih[d]      + dot9(s_gWih + d*12,        mg)
                          + s_gbhh[d]      + dot9(s_gWhh + d*12,        h);
                float a1  = s_gbih[9+d]    + dot9(s_gWih + (9+d)*12,    mg)
                          + s_gbhh[9+d]    + dot9(s_gWhh + (9+d)*12,    h);
                float gx2 = s_gbih[18+d]   + dot9(s_gWih + (18+d)*12,   mg);
                float gh2 = s_gbhh[18+d]   + dot9(s_gWhh + (18+d)*12,   h);
                float r  = fsigmoid(a0);
                float z  = fsigmoid(a1);
                float nn = ftanh_(fmaf(r, gh2, gx2));
                hn[d] = fmaf(z, h[d] - nn, nn) * vm;   // ((1-z)*n + z*h) * valid
            }
            #pragma unroll
            for (int d = 0; d < 9; d++) h[d] = hn[d];
        }
        __syncthreads();
    }

    // ---- store hidden for LSTM input, readout p0 ----
    if (act) {
        #pragma unroll
        for (int d = 0; d < 9; d++) s_x[tid*12 + d] = h[d];
        float q[9];
        #pragma unroll
        for (int d = 0; d < 9; d++)
            q[d] = fmaxf(s_ro1b[d] + dot9(s_ro1W + d*12, h), 0.0f);
        size_t base = ((size_t)n * NODES + tid) * 7;
        #pragma unroll
        for (int k = 0; k < 7; k++)
            out_p0[base + k] = (s_ro2b[k] + dot9(s_ro2W + k*12, q)) * vm;
    }
    __syncthreads();

    // ================= Bi-LSTM: 12 chains x 16-lane subgroups, shfl h-exchange =================
    {
        const int g    = tid >> 4;           // 0..11 chain id (never crosses warp)
        const int l16  = tid & 15;
        const int d2   = (l16 < 9) ? l16 : 8;  // clamp inactive lanes (no OOB reads)
        const bool lw  = (l16 < 9);
        const int dirn = g / 6;              // 0 fwd, 1 bwd
        const int lm   = g % 6;

        // register-resident weights: this thread's 8 rows + 4 biases
        const float* Wi = s_lWih[dirn];
        const float* Wh = s_lWhh[dirn];
        float wi[4][9], wh[4][9], bg[4];
        #pragma unroll
        for (int k = 0; k < 4; k++) {
            load9(wi[k], Wi + (k*9 + d2)*12);
            load9(wh[k], Wh + (k*9 + d2)*12);
            bg[k] = s_lb[dirn][k*9 + d2];
        }

        float c = 0.0f, hd = 0.0f;
        const float* xrow = s_x + (dirn ? ((TT-1)*6 + lm)*12 : lm*12);
        const int    xstep = dirn ? -6*12 : 6*12;
        float*       orow = s_buf + (dirn ? ((TT-1)*6 + lm)*STRIDE_OUT : lm*STRIDE_OUT)
                          + dirn*9 + d2;
        const int    ostep = dirn ? -6*STRIDE_OUT : 6*STRIDE_OUT;

        for (int s = 0; s < TT; s++) {
            float hr[9];
            #pragma unroll
            for (int j = 0; j < 9; j++)
                hr[j] = __shfl_sync(0xffffffffu, hd, j, 16);
            float xr[9];
            load9(xr, xrow);
            float g0 = bg[0] + dot9r(wi[0], xr) + dot9r(wh[0], hr);
            float g1 = bg[1] + dot9r(wi[1], xr) + dot9r(wh[1], hr);
            float g2 = bg[2] + dot9r(wi[2], xr) + dot9r(wh[2], hr);
            float g3 = bg[3] + dot9r(wi[3], xr) + dot9r(wh[3], hr);
            float i_ = fsigmoid(g0);
            float f_ = fsigmoid(g1);
            float gg = ftanh_(g2);
            float o_ = fsigmoid(g3);
            c  = fmaf(f_, c, i_ * gg);
            hd = o_ * ftanh_(c);
            if (lw) *orow = hd;
            xrow += xstep; orow += ostep;
        }
    }
    __syncthreads();

    // ================= final readout p (thread = node (t,m)) =================
    if (act) {
        float o18[18];
        const float* op = s_buf + tid*STRIDE_OUT;
        #pragma unroll
        for (int k = 0; k < 18; k++) o18[k] = op[k];
        float q[9];
        #pragma unroll
        for (int dd = 0; dd < 9; dd++) {
            const float* w = s_lr1W + dd*20;
            float acc = 0.0f;
            #pragma unroll
            for (int qq = 0; qq < 4; qq++) {
                float4 a = *(const float4*)(w + 4*qq);
                acc = fmaf(a.x, o18[4*qq+0], acc);
                acc = fmaf(a.y, o18[4*qq+1], acc);
                acc = fmaf(a.z, o18[4*qq+2], acc);
                acc = fmaf(a.w, o18[4*qq+3], acc);
            }
            acc = fmaf(w[16], o18[16], acc);
            acc = fmaf(w[17], o18[17], acc);
            q[dd] = fmaxf(s_lr1b[dd] + acc, 0.0f);
        }
        size_t base = ((size_t)n * NODES + tid) * 7;
        #pragma unroll
        for (int k = 0; k < 7; k++)
            out_p[base + k] = (s_lr2b[k] + dot9(s_lr2W + k*12, q)) * vm;
    }
}

extern "C" void kernel_launch(void* const* d_in, const int* in_sizes, int n_in,
                              void* d_out, int out_size)
{
    const float* nf    = (const float*)d_in[0];
    const float* pos   = (const float*)d_in[1];
    const float* attm  = (const float*)d_in[2];
    const float* msgW  = (const float*)d_in[3];
    const float* msgb  = (const float*)d_in[4];
    const float* gWih  = (const float*)d_in[5];
    const float* gWhh  = (const float*)d_in[6];
    const float* gbih  = (const float*)d_in[7];
    const float* gbhh  = (const float*)d_in[8];
    const float* ro1W  = (const float*)d_in[9];
    const float* ro1b  = (const float*)d_in[10];
    const float* ro2W  = (const float*)d_in[11];
    const float* ro2b  = (const float*)d_in[12];
    const float* lfWih = (const float*)d_in[13];
    const float* lfWhh = (const float*)d_in[14];
    const float* lfbih = (const float*)d_in[15];
    const float* lfbhh = (const float*)d_in[16];
    const float* lbWih = (const float*)d_in[17];
    const float* lbWhh = (const float*)d_in[18];
    const float* lbbih = (const float*)d_in[19];
    const float* lbbhh = (const float*)d_in[20];
    const float* lr1W  = (const float*)d_in[21];
    const float* lr1b  = (const float*)d_in[22];
    const float* lr2W  = (const float*)d_in[23];
    const float* lr2b  = (const float*)d_in[24];
    const int*   nrec  = (const int*)d_in[25];

    int N = in_sizes[25] / TT;
    float* out = (float*)d_out;
    size_t half = (size_t)N * TT * MM * 7;   // pred_label first, pred_label0 second

    gnn_lstm_kernel<<<N, NTHREADS>>>(
        nf, pos, attm, msgW, msgb, gWih, gWhh, gbih, gbhh,
        ro1W, ro1b, ro2W, ro2b,
        lfWih, lfWhh, lfbih, lfbhh, lbWih, lbWhh, lbbih, lbbhh,
        lr1W, lr1b, lr2W, lr2b, nrec,
        out, out + half);
}

// round 3
// speedup vs baseline: 1.3365x; 1.3365x over previous
#include <cuda_runtime.h>

#define TT 20
#define MM 6
#define MAXN 8192

// scratch (allocation-free rule: __device__ globals)
__device__ __align__(16) float g_hidden[(size_t)TT * MAXN * MM * 12];
__device__ __align__(16) float g_lstm[2][(size_t)TT * MAXN * MM * 12];

// ---------------- MUFU activations ----------------
__device__ __forceinline__ float fsig(float x) {
    float e, r;
    asm("ex2.approx.f32 %0, %1;" : "=f"(e) : "f"(x * -1.4426950408889634f));
    asm("rcp.approx.f32 %0, %1;" : "=f"(r) : "f"(1.0f + e));
    return r;
}
__device__ __forceinline__ float ftanh_(float x) {
    float e, r;
    asm("ex2.approx.f32 %0, %1;" : "=f"(e) : "f"(x * -2.8853900817779268f));
    asm("rcp.approx.f32 %0, %1;" : "=f"(r) : "f"(1.0f + e));
    return fmaf(2.0f, r, -1.0f);
}

// ---------------- dot helpers ----------------
__device__ __forceinline__ float dot9(const float* __restrict__ w, const float* r) {
    float4 a = *(const float4*)w;
    float4 b = *(const float4*)(w + 4);
    float acc = w[8] * r[8];
    acc = fmaf(a.x, r[0], acc); acc = fmaf(a.y, r[1], acc);
    acc = fmaf(a.z, r[2], acc); acc = fmaf(a.w, r[3], acc);
    acc = fmaf(b.x, r[4], acc); acc = fmaf(b.y, r[5], acc);
    acc = fmaf(b.z, r[6], acc); acc = fmaf(b.w, r[7], acc);
    return acc;
}
__device__ __forceinline__ void load9(float* r, const float* __restrict__ p) {
    float4 a = *(const float4*)p;
    float4 b = *(const float4*)(p + 4);
    r[0]=a.x; r[1]=a.y; r[2]=a.z; r[3]=a.w;
    r[4]=b.x; r[5]=b.y; r[6]=b.z; r[7]=b.w;
    r[8]=p[8];
}
__device__ __forceinline__ void store9(float* __restrict__ p, const float* r) {
    *(float4*)p       = make_float4(r[0], r[1], r[2], r[3]);
    *(float4*)(p + 4) = make_float4(r[4], r[5], r[6], r[7]);
    p[8] = r[8];
}

// ================= K1: GRU message passing + p0 readout =================
// thread = node; 192 threads = 32 (n,t)-groups x 6 nodes. All lanes active.
__global__ __launch_bounds__(192)
void k1_gru(const float* __restrict__ nf, const float* __restrict__ pos,
            const float* __restrict__ attm,
            const float* __restrict__ msgW, const float* __restrict__ msgb,
            const float* __restrict__ gWih, const float* __restrict__ gWhh,
            const float* __restrict__ gbih, const float* __restrict__ gbhh,
            const float* __restrict__ ro1W, const float* __restrict__ ro1b,
            const float* __restrict__ ro2W, const float* __restrict__ ro2b,
            const int* __restrict__ numrec, float* __restrict__ out_p0, int N)
{
    __shared__ __align__(16) float s_msgW[9*12], s_gWih[27*12], s_gWhh[27*12];
    __shared__ __align__(16) float s_ro1W[9*12], s_ro2W[7*12];
    __shared__ __align__(16) float s_msgb[12], s_gbih[28], s_gbhh[28], s_ro1b[12], s_ro2b[8];
    __shared__ __align__(16) float s_msg[192*12];

    const int tid = threadIdx.x;
    for (int i = tid; i < 81;  i += 192) s_msgW[(i/9)*12 + i%9] = msgW[i];
    for (int i = tid; i < 243; i += 192) s_gWih[(i/9)*12 + i%9] = gWih[i];
    for (int i = tid; i < 243; i += 192) s_gWhh[(i/9)*12 + i%9] = gWhh[i];
    for (int i = tid; i < 81;  i += 192) s_ro1W[(i/9)*12 + i%9] = ro1W[i];
    for (int i = tid; i < 63;  i += 192) s_ro2W[(i/9)*12 + i%9] = ro2W[i];
    if (tid < 9)  s_msgb[tid] = msgb[tid];
    if (tid < 27) { s_gbih[tid] = gbih[tid]; s_gbhh[tid] = gbhh[tid]; }
    if (tid < 9)  s_ro1b[tid] = ro1b[tid];
    if (tid < 7)  s_ro2b[tid] = ro2b[tid];

    const int g = tid / 6, m = tid % 6;
    const int ntot = N * TT;
    int nt = blockIdx.x * 32 + g;
    const bool vnt = nt < ntot;
    if (!vnt) nt = 0;
    const int n = nt / TT, t = nt % TT;
    const int nr0 = numrec[(size_t)n * TT];
    const float vm = (m < nr0) ? 1.0f : 0.0f;

    float h[9], attr[6];
    {
        const float* q = nf + (size_t)nt*18 + m*3;
        h[0]=q[0]; h[1]=q[1]; h[2]=q[2];
        const float* pq = pos + (size_t)nt*36 + m*6;
        #pragma unroll
        for (int j = 0; j < 6; j++) h[3+j] = pq[j];
        const float* aq = attm + (size_t)nt*36 + m*6;
        #pragma unroll
        for (int j = 0; j < 6; j++) attr[j] = (j < nr0) ? aq[j] : 0.0f;
    }
    __syncthreads();

    #pragma unroll
    for (int rd = 0; rd < 2; rd++) {
        float msg[9];
        #pragma unroll
        for (int gg = 0; gg < 9; gg++) msg[gg] = s_msgb[gg] + dot9(s_msgW + gg*12, h);
        store9(s_msg + tid*12, msg);
        __syncthreads();
        float mg[9];
        #pragma unroll
        for (int d = 0; d < 9; d++) mg[d] = 0.0f;
        #pragma unroll
        for (int j = 0; j < 6; j++) {
            float pm[9]; load9(pm, s_msg + (g*6 + j)*12);
            float aj = attr[j];
            #pragma unroll
            for (int d = 0; d < 9; d++) mg[d] = fmaf(aj, pm[d], mg[d]);
        }
        float hn[9];
        #pragma unroll
        for (int d = 0; d < 9; d++) {
            float a0  = s_gbih[d]    + s_gbhh[d]
                      + dot9(s_gWih + d*12, mg)      + dot9(s_gWhh + d*12, h);
            float a1  = s_gbih[9+d]  + s_gbhh[9+d]
                      + dot9(s_gWih + (9+d)*12, mg)  + dot9(s_gWhh + (9+d)*12, h);
            float gx2 = s_gbih[18+d] + dot9(s_gWih + (18+d)*12, mg);
            float gh2 = s_gbhh[18+d] + dot9(s_gWhh + (18+d)*12, h);
            float r  = fsig(a0);
            float z  = fsig(a1);
            float nn = ftanh_(fmaf(r, gh2, gx2));
            hn[d] = fmaf(z, h[d] - nn, nn) * vm;
        }
        #pragma unroll
        for (int d = 0; d < 9; d++) h[d] = hn[d];
        __syncthreads();
    }

    if (vnt) {
        store9(g_hidden + ((size_t)t * (N*MM) + n*MM + m) * 12, h);
        float q[9];
        #pragma unroll
        for (int d = 0; d < 9; d++)
            q[d] = fmaxf(s_ro1b[d] + dot9(s_ro1W + d*12, h), 0.0f);
        float* po = out_p0 + ((size_t)n*(TT*MM) + t*MM + m) * 7;
        #pragma unroll
        for (int k = 0; k < 7; k++)
            po[k] = (s_ro2b[k] + dot9(s_ro2W + k*12, q)) * vm;
    }
}

// ================= K2: Bi-LSTM, thread = one chain (n,m,dir) =================
__global__ __launch_bounds__(256)
void k2_lstm(const float* __restrict__ lfWih, const float* __restrict__ lfWhh,
             const float* __restrict__ lfbih, const float* __restrict__ lfbhh,
             const float* __restrict__ lbWih, const float* __restrict__ lbWhh,
             const float* __restrict__ lbbih, const float* __restrict__ lbbhh,
             int N)
{
    __shared__ __align__(16) float s_Wi[2][36*12], s_Wh[2][36*12];
    __shared__ __align__(16) float s_b[2][40];

    const int tid = threadIdx.x;
    for (int i = tid; i < 324; i += 256) {
        int r = i / 9, cc = i % 9;
        s_Wi[0][r*12+cc] = lfWih[i];
        s_Wi[1][r*12+cc] = lbWih[i];
        s_Wh[0][r*12+cc] = lfWhh[i];
        s_Wh[1][r*12+cc] = lbWhh[i];
    }
    if (tid < 36) { s_b[0][tid] = lfbih[tid] + lfbhh[tid];
                    s_b[1][tid] = lbbih[tid] + lbbhh[tid]; }
    __syncthreads();

    const int half = N * MM;
    const int cid = blockIdx.x * 256 + tid;
    if (cid >= 2*half) return;
    const int dirn = (cid >= half) ? 1 : 0;   // warp-uniform (half % 256 == 0 for N=8192)
    const int nm = cid - dirn*half;

    const float* Wi = s_Wi[dirn];
    const float* Wh = s_Wh[dirn];
    const float* bb = s_b[dirn];

    float h[9], c[9];
    #pragma unroll
    for (int d = 0; d < 9; d++) { h[d] = 0.0f; c[d] = 0.0f; }

    const long  tstep = (long)half * 12;
    const long  sstep = dirn ? -tstep : tstep;
    const float* xp = g_hidden + (size_t)nm*12 + (dirn ? (size_t)(TT-1)*tstep : 0);
    float*       op = g_lstm[dirn] + (size_t)nm*12 + (dirn ? (size_t)(TT-1)*tstep : 0);

    float x[9];
    load9(x, xp);
    for (int s = 0; s < TT; s++) {
        xp += sstep;
        float xn[9];
        if (s < TT-1) load9(xn, xp);      // prefetch next step's input
        float hn[9];
        #pragma unroll
        for (int d = 0; d < 9; d++) {
            float g0 = bb[d]      + dot9(Wi + d*12,      x) + dot9(Wh + d*12,      h);
            float g1 = bb[9+d]    + dot9(Wi + (9+d)*12,  x) + dot9(Wh + (9+d)*12,  h);
            float g2 = bb[18+d]   + dot9(Wi + (18+d)*12, x) + dot9(Wh + (18+d)*12, h);
            float g3 = bb[27+d]   + dot9(Wi + (27+d)*12, x) + dot9(Wh + (27+d)*12, h);
            float i_ = fsig(g0);
            float f_ = fsig(g1);
            float gg = ftanh_(g2);
            float o_ = fsig(g3);
            c[d]  = fmaf(f_, c[d], i_ * gg);
            hn[d] = o_ * ftanh_(c[d]);
        }
        #pragma unroll
        for (int d = 0; d < 9; d++) h[d] = hn[d];
        store9(op, h);
        op += sstep;
        #pragma unroll
        for (int d = 0; d < 9; d++) x[d] = xn[d];
    }
}

// ================= K3: final readout p =================
__global__ __launch_bounds__(256)
void k3_readout(const float* __restrict__ lr1W, const float* __restrict__ lr1b,
                const float* __restrict__ lr2W, const float* __restrict__ lr2b,
                const int* __restrict__ numrec, float* __restrict__ out_p, int N)
{
    __shared__ __align__(16) float s_lr1W[9*20], s_lr2W[7*12];
    __shared__ __align__(16) float s_lr1b[12], s_lr2b[8];

    const int tid = threadIdx.x;
    for (int i = tid; i < 162; i += 256) s_lr1W[(i/18)*20 + i%18] = lr1W[i];
    for (int i = tid; i < 63;  i += 256) s_lr2W[(i/9)*12 + i%9]  = lr2W[i];
    if (tid < 9) s_lr1b[tid] = lr1b[tid];
    if (tid < 7) s_lr2b[tid] = lr2b[tid];
    __syncthreads();

    const int half = N * MM;
    const int id = blockIdx.x * 256 + tid;
    if (id >= TT * half) return;
    const int t = id / half;
    const int nm = id - t * half;

    float o18[18];
    load9(o18,     g_lstm[0] + ((size_t)t*half + nm)*12);
    load9(o18 + 9, g_lstm[1] + ((size_t)t*half + nm)*12);

    float q[9];
    #pragma unroll
    for (int d = 0; d < 9; d++) {
        const float* w = s_lr1W + d*20;
        float acc = s_lr1b[d];
        #pragma unroll
        for (int qq = 0; qq < 4; qq++) {
            float4 a = *(const float4*)(w + 4*qq);
            acc = fmaf(a.x, o18[4*qq+0], acc);
            acc = fmaf(a.y, o18[4*qq+1], acc);
            acc = fmaf(a.z, o18[4*qq+2], acc);
            acc = fmaf(a.w, o18[4*qq+3], acc);
        }
        acc = fmaf(w[16], o18[16], acc);
        acc = fmaf(w[17], o18[17], acc);
        q[d] = fmaxf(acc, 0.0f);
    }

    const int n = nm / MM, m = nm - n*MM;
    const int nr0 = numrec[(size_t)n * TT];
    const float vm = (m < nr0) ? 1.0f : 0.0f;
    float* po = out_p + ((size_t)n*(TT*MM) + t*MM + m) * 7;
    #pragma unroll
    for (int k = 0; k < 7; k++)
        po[k] = (s_lr2b[k] + dot9(s_lr2W + k*12, q)) * vm;
}

extern "C" void kernel_launch(void* const* d_in, const int* in_sizes, int n_in,
                              void* d_out, int out_size)
{
    const float* nf    = (const float*)d_in[0];
    const float* pos   = (const float*)d_in[1];
    const float* attm  = (const float*)d_in[2];
    const float* msgW  = (const float*)d_in[3];
    const float* msgb  = (const float*)d_in[4];
    const float* gWih  = (const float*)d_in[5];
    const float* gWhh  = (const float*)d_in[6];
    const float* gbih  = (const float*)d_in[7];
    const float* gbhh  = (const float*)d_in[8];
    const float* ro1W  = (const float*)d_in[9];
    const float* ro1b  = (const float*)d_in[10];
    const float* ro2W  = (const float*)d_in[11];
    const float* ro2b  = (const float*)d_in[12];
    const float* lfWih = (const float*)d_in[13];
    const float* lfWhh = (const float*)d_in[14];
    const float* lfbih = (const float*)d_in[15];
    const float* lfbhh = (const float*)d_in[16];
    const float* lbWih = (const float*)d_in[17];
    const float* lbWhh = (const float*)d_in[18];
    const float* lbbih = (const float*)d_in[19];
    const float* lbbhh = (const float*)d_in[20];
    const float* lr1W  = (const float*)d_in[21];
    const float* lr1b  = (const float*)d_in[22];
    const float* lr2W  = (const float*)d_in[23];
    const float* lr2b  = (const float*)d_in[24];
    const int*   nrec  = (const int*)d_in[25];

    const int N = in_sizes[25] / TT;
    float* out = (float*)d_out;
    float* out_p  = out;                              // pred_label
    float* out_p0 = out + (size_t)N * TT * MM * 7;    // pred_label0

    const int grid1 = (N*TT + 31) / 32;
    const int grid2 = (N*MM*2 + 255) / 256;
    const int grid3 = (N*TT*MM + 255) / 256;

    k1_gru<<<grid1, 192>>>(nf, pos, attm, msgW, msgb, gWih, gWhh, gbih, gbhh,
                           ro1W, ro1b, ro2W, ro2b, nrec, out_p0, N);
    k2_lstm<<<grid2, 256>>>(lfWih, lfWhh, lfbih, lfbhh,
                            lbWih, lbWhh, lbbih, lbbhh, N);
    k3_readout<<<grid3, 256>>>(lr1W, lr1b, lr2W, lr2b, nrec, out_p, N);
}

// round 4
// speedup vs baseline: 1.4750x; 1.1036x over previous
#include <cuda_runtime.h>

#define TT 20
#define MM 6
#define MAXN 8192
typedef unsigned long long u64;

// scratch (allocation-free rule: __device__ globals)
__device__ __align__(16) float g_hidden[(size_t)TT * MAXN * MM * 12];
__device__ __align__(16) float g_lstm[2][(size_t)TT * MAXN * MM * 12];

// ---------------- f32x2 helpers ----------------
__device__ __forceinline__ u64 pk(float a, float b) {
    u64 r; asm("mov.b64 %0, {%1, %2};" : "=l"(r) : "f"(a), "f"(b)); return r;
}
__device__ __forceinline__ void upk(float& a, float& b, u64 v) {
    asm("mov.b64 {%0, %1}, %2;" : "=f"(a), "=f"(b) : "l"(v));
}
__device__ __forceinline__ u64 ffma2(u64 a, u64 b, u64 c) {
    u64 r; asm("fma.rn.f32x2 %0, %1, %2, %3;" : "=l"(r) : "l"(a), "l"(b), "l"(c)); return r;
}

// packed 9-dot: W[0..8] (pairs), v[0..8] (pairs)
__device__ __forceinline__ u64 dotp9(const u64* __restrict__ W, const u64* v, u64 acc) {
    #pragma unroll
    for (int kk = 0; kk < 4; kk++) {
        ulonglong2 w = *(const ulonglong2*)(W + 2*kk);
        acc = ffma2(w.x, v[2*kk],   acc);
        acc = ffma2(w.y, v[2*kk+1], acc);
    }
    acc = ffma2(W[8], v[8], acc);
    return acc;
}
// packed 18-dot: W[0..8] vs va, W[10..18] vs vb (10-offset keeps 16B alignment)
__device__ __forceinline__ u64 dotp18(const u64* __restrict__ W, const u64* va, const u64* vb, u64 acc) {
    acc = dotp9(W, va, acc);
    acc = dotp9(W + 10, vb, acc);
    return acc;
}

// ---------------- MUFU activations ----------------
__device__ __forceinline__ float fsig(float x) {
    float e, r;
    asm("ex2.approx.f32 %0, %1;" : "=f"(e) : "f"(x * -1.4426950408889634f));
    asm("rcp.approx.f32 %0, %1;" : "=f"(r) : "f"(1.0f + e));
    return r;
}
__device__ __forceinline__ float ftanh_(float x) {
    float e, r;
    asm("ex2.approx.f32 %0, %1;" : "=f"(e) : "f"(x * -2.8853900817779268f));
    asm("rcp.approx.f32 %0, %1;" : "=f"(r) : "f"(1.0f + e));
    return fmaf(2.0f, r, -1.0f);
}

// ---------------- scalar dot helpers ----------------
__device__ __forceinline__ float dot9(const float* __restrict__ w, const float* r) {
    float4 a = *(const float4*)w;
    float4 b = *(const float4*)(w + 4);
    float acc = w[8] * r[8];
    acc = fmaf(a.x, r[0], acc); acc = fmaf(a.y, r[1], acc);
    acc = fmaf(a.z, r[2], acc); acc = fmaf(a.w, r[3], acc);
    acc = fmaf(b.x, r[4], acc); acc = fmaf(b.y, r[5], acc);
    acc = fmaf(b.z, r[6], acc); acc = fmaf(b.w, r[7], acc);
    return acc;
}
__device__ __forceinline__ void load9(float* r, const float* __restrict__ p) {
    float4 a = *(const float4*)p;
    float4 b = *(const float4*)(p + 4);
    r[0]=a.x; r[1]=a.y; r[2]=a.z; r[3]=a.w;
    r[4]=b.x; r[5]=b.y; r[6]=b.z; r[7]=b.w;
    r[8]=p[8];
}
__device__ __forceinline__ void store9(float* __restrict__ p, const float* r) {
    *(float4*)p       = make_float4(r[0], r[1], r[2], r[3]);
    *(float4*)(p + 4) = make_float4(r[4], r[5], r[6], r[7]);
    p[8] = r[8];
}

// ================= K1: GRU message passing + p0 readout =================
__global__ __launch_bounds__(192)
void k1_gru(const float* __restrict__ nf, const float* __restrict__ pos,
            const float* __restrict__ attm,
            const float* __restrict__ msgW, const float* __restrict__ msgb,
            const float* __restrict__ gWih, const float* __restrict__ gWhh,
            const float* __restrict__ gbih, const float* __restrict__ gbhh,
            const float* __restrict__ ro1W, const float* __restrict__ ro1b,
            const float* __restrict__ ro2W, const float* __restrict__ ro2b,
            const int* __restrict__ numrec, float* __restrict__ out_p0, int N)
{
    __shared__ __align__(16) u64 s_PM[4][10];     // msg rows (2p,2p+1) packed
    __shared__ __align__(16) u64 s_P1[9][20];     // [0..8] Wih(d,9+d), [10..18] Whh(d,9+d)
    __shared__ __align__(16) u64 s_P3[9][10];     // (Wih[18+d], Whh[18+d]) packed
    __shared__ __align__(16) u64 s_bA[9], s_b3[9], s_bm[4];
    __shared__ __align__(16) float s_msgW8[12], s_ro1W[9*12], s_ro2W[7*12];
    __shared__ __align__(16) float s_ro1b[12], s_ro2b[8];
    __shared__ float s_bm8;
    __shared__ __align__(16) float s_msg[192*12];

    const int tid = threadIdx.x;
    // ---- staging (pre-packed weights) ----
    for (int i = tid; i < 36; i += 192) {
        int p = i/9, k = i%9;
        ((float2*)s_PM)[p*10 + k] = make_float2(msgW[(2*p)*9 + k], msgW[(2*p+1)*9 + k]);
    }
    for (int i = tid; i < 162; i += 192) {
        int d = i/18, k = i%18;
        float lo, hi; int idx;
        if (k < 9) { lo = gWih[d*9+k];        hi = gWih[(9+d)*9+k];        idx = d*20 + k; }
        else { int kk = k-9; lo = gWhh[d*9+kk]; hi = gWhh[(9+d)*9+kk];     idx = d*20 + 10 + kk; }
        ((float2*)s_P1)[idx] = make_float2(lo, hi);
    }
    for (int i = tid; i < 81; i += 192) {
        int d = i/9, k = i%9;
        ((float2*)s_P3)[d*10 + k] = make_float2(gWih[(18+d)*9+k], gWhh[(18+d)*9+k]);
    }
    if (tid < 4) ((float2*)s_bm)[tid] = make_float2(msgb[2*tid], msgb[2*tid+1]);
    if (tid == 4) s_bm8 = msgb[8];
    if (tid < 9) {
        ((float2*)s_bA)[tid] = make_float2(gbih[tid] + gbhh[tid], gbih[9+tid] + gbhh[9+tid]);
        ((float2*)s_b3)[tid] = make_float2(gbih[18+tid], gbhh[18+tid]);
        s_msgW8[tid] = msgW[8*9 + tid];
        s_ro1b[tid] = ro1b[tid];
    }
    for (int i = tid; i < 81; i += 192) s_ro1W[(i/9)*12 + i%9] = ro1W[i];
    for (int i = tid; i < 63; i += 192) s_ro2W[(i/9)*12 + i%9] = ro2W[i];
    if (tid < 7) s_ro2b[tid] = ro2b[tid];

    const int g = tid / 6, m = tid % 6;
    const int ntot = N * TT;
    int nt = blockIdx.x * 32 + g;
    const bool vnt = nt < ntot;
    if (!vnt) nt = 0;
    const int n = nt / TT, t = nt % TT;
    const int nr0 = numrec[(size_t)n * TT];
    const float vm = (m < nr0) ? 1.0f : 0.0f;

    float h[9], attr[6];
    {
        const float* q = nf + (size_t)nt*18 + m*3;
        h[0]=q[0]; h[1]=q[1]; h[2]=q[2];
        const float* pq = pos + (size_t)nt*36 + m*6;
        #pragma unroll
        for (int j = 0; j < 6; j++) h[3+j] = pq[j];
        const float* aq = attm + (size_t)nt*36 + m*6;
        #pragma unroll
        for (int j = 0; j < 6; j++) attr[j] = (j < nr0) ? aq[j] : 0.0f;
    }
    u64 a2[6];
    #pragma unroll
    for (int j = 0; j < 6; j++) a2[j] = pk(attr[j], attr[j]);
    __syncthreads();

    #pragma unroll
    for (int rd = 0; rd < 2; rd++) {
        u64 hd2[9];
        #pragma unroll
        for (int k = 0; k < 9; k++) hd2[k] = pk(h[k], h[k]);
        // msg = W_msg h + b  (4 packed row-pairs + row 8 scalar)
        float msg[9];
        #pragma unroll
        for (int p = 0; p < 4; p++) {
            u64 acc = dotp9(&s_PM[p][0], hd2, s_bm[p]);
            upk(msg[2*p], msg[2*p+1], acc);
        }
        msg[8] = s_bm8 + dot9(s_msgW8, h);
        store9(s_msg + tid*12, msg);
        __syncthreads();
        // mg = sum_j att_j * msg_j   (packed pairs)
        u64 mgp[4] = {0,0,0,0};
        float mg8 = 0.0f;
        #pragma unroll
        for (int j = 0; j < 6; j++) {
            const float* mp = s_msg + (g*6 + j)*12;
            const u64* mpp = (const u64*)mp;
            mgp[0] = ffma2(a2[j], mpp[0], mgp[0]);
            mgp[1] = ffma2(a2[j], mpp[1], mgp[1]);
            mgp[2] = ffma2(a2[j], mpp[2], mgp[2]);
            mgp[3] = ffma2(a2[j], mpp[3], mgp[3]);
            mg8 = fmaf(attr[j], mp[8], mg8);
        }
        float mg[9];
        #pragma unroll
        for (int p = 0; p < 4; p++) upk(mg[2*p], mg[2*p+1], mgp[p]);
        mg[8] = mg8;
        u64 mg2[9], mh2[9];
        #pragma unroll
        for (int k = 0; k < 9; k++) { mg2[k] = pk(mg[k], mg[k]); mh2[k] = pk(mg[k], h[k]); }
        // GRU cell
        float hn[9];
        #pragma unroll
        for (int d = 0; d < 9; d++) {
            u64 acc1 = dotp18(&s_P1[d][0], mg2, hd2, s_bA[d]);   // (r_pre, z_pre)
            u64 acc3 = dotp9(&s_P3[d][0], mh2, s_b3[d]);         // (gx2, gh2)
            float a0, a1, gx2, gh2;
            upk(a0, a1, acc1);
            upk(gx2, gh2, acc3);
            float r  = fsig(a0);
            float z  = fsig(a1);
            float nn = ftanh_(fmaf(r, gh2, gx2));
            hn[d] = fmaf(z, h[d] - nn, nn) * vm;
        }
        #pragma unroll
        for (int d = 0; d < 9; d++) h[d] = hn[d];
        __syncthreads();
    }

    if (vnt) {
        store9(g_hidden + ((size_t)t * (N*MM) + n*MM + m) * 12, h);
        float q[9];
        #pragma unroll
        for (int d = 0; d < 9; d++)
            q[d] = fmaxf(s_ro1b[d] + dot9(s_ro1W + d*12, h), 0.0f);
        float* po = out_p0 + ((size_t)n*(TT*MM) + t*MM + m) * 7;
        #pragma unroll
        for (int k = 0; k < 7; k++)
            po[k] = (s_ro2b[k] + dot9(s_ro2W + k*12, q)) * vm;
    }
}

// ================= K2: Bi-LSTM, thread = one chain (n,m,dir) =================
__global__ __launch_bounds__(128)
void k2_lstm(const float* __restrict__ lfWih, const float* __restrict__ lfWhh,
             const float* __restrict__ lfbih, const float* __restrict__ lfbhh,
             const float* __restrict__ lbWih, const float* __restrict__ lbWhh,
             const float* __restrict__ lbbih, const float* __restrict__ lbbhh,
             int N)
{
    // per dirn, per d: [0..8] Wi rows (d,9+d) packed; [10..18] Wh rows (d,9+d)
    __shared__ __align__(16) u64 s_WA[2][9][20];  // gates (i,f)
    __shared__ __align__(16) u64 s_WB[2][9][20];  // gates (g,o)
    __shared__ __align__(16) u64 s_bA2[18], s_bB2[18];

    const int tid = threadIdx.x;
    for (int i = tid; i < 324; i += 128) {
        int dirn = i / 162, r = i % 162, d = r/18, k = r%18;
        const float* Wi = dirn ? lbWih : lfWih;
        const float* Wh = dirn ? lbWhh : lfWhh;
        float loA, hiA, loB, hiB; int idx;
        if (k < 9) {
            loA = Wi[d*9+k];      hiA = Wi[(9+d)*9+k];
            loB = Wi[(18+d)*9+k]; hiB = Wi[(27+d)*9+k];
            idx = k;
        } else {
            int kk = k - 9;
            loA = Wh[d*9+kk];      hiA = Wh[(9+d)*9+kk];
            loB = Wh[(18+d)*9+kk]; hiB = Wh[(27+d)*9+kk];
            idx = 10 + kk;
        }
        ((float2*)&s_WA[dirn][d][0])[idx] = make_float2(loA, hiA);
        ((float2*)&s_WB[dirn][d][0])[idx] = make_float2(loB, hiB);
    }
    if (tid < 18) {
        int dirn = tid / 9, d = tid % 9;
        const float* bi = dirn ? lbbih : lfbih;
        const float* bh = dirn ? lbbhh : lfbhh;
        ((float2*)s_bA2)[tid] = make_float2(bi[d] + bh[d],       bi[9+d] + bh[9+d]);
        ((float2*)s_bB2)[tid] = make_float2(bi[18+d] + bh[18+d], bi[27+d] + bh[27+d]);
    }
    __syncthreads();

    const int half = N * MM;
    const int cid = blockIdx.x * 128 + tid;
    if (cid >= 2*half) return;
    const int dirn = (cid >= half) ? 1 : 0;   // warp-uniform (half % 128 == 0)
    const int nm = cid - dirn*half;

    const u64* WA = &s_WA[dirn][0][0];
    const u64* WB = &s_WB[dirn][0][0];
    const u64* bA = s_bA2 + dirn*9;
    const u64* bB = s_bB2 + dirn*9;

    float h[9], c[9];
    #pragma unroll
    for (int d = 0; d < 9; d++) { h[d] = 0.0f; c[d] = 0.0f; }

    const long  tstep = (long)half * 12;
    const long  sstep = dirn ? -tstep : tstep;
    const float* xp = g_hidden + (size_t)nm*12 + (dirn ? (size_t)(TT-1)*tstep : 0);
    float*       op = g_lstm[dirn] + (size_t)nm*12 + (dirn ? (size_t)(TT-1)*tstep : 0);

    float x[9];
    load9(x, xp);
    for (int s = 0; s < TT; s++) {
        xp += sstep;
        float xn[9];
        if (s < TT-1) load9(xn, xp);      // prefetch next step's input
        u64 xx[9], hh[9];
        #pragma unroll
        for (int k = 0; k < 9; k++) { xx[k] = pk(x[k], x[k]); hh[k] = pk(h[k], h[k]); }
        #pragma unroll
        for (int d = 0; d < 9; d++) {
            u64 accA = dotp18(WA + d*20, xx, hh, bA[d]);   // (i_pre, f_pre)
            u64 accB = dotp18(WB + d*20, xx, hh, bB[d]);   // (g_pre, o_pre)
            float gi, gf, gG, go;
            upk(gi, gf, accA);
            upk(gG, go, accB);
            float i_ = fsig(gi);
            float f_ = fsig(gf);
            float gg = ftanh_(gG);
            float o_ = fsig(go);
            c[d] = fmaf(f_, c[d], i_ * gg);
            h[d] = o_ * ftanh_(c[d]);      // safe: hh already packed
        }
        store9(op, h);
        op += sstep;
        #pragma unroll
        for (int d = 0; d < 9; d++) x[d] = xn[d];
    }
}

// ================= K3: final readout p =================
__global__ __launch_bounds__(256)
void k3_readout(const float* __restrict__ lr1W, const float* __restrict__ lr1b,
                const float* __restrict__ lr2W, const float* __restrict__ lr2b,
                const int* __restrict__ numrec, float* __restrict__ out_p, int N)
{
    __shared__ __align__(16) float s_lr1W[9*20], s_lr2W[7*12];
    __shared__ __align__(16) float s_lr1b[12], s_lr2b[8];

    const int tid = threadIdx.x;
    for (int i = tid; i < 162; i += 256) s_lr1W[(i/18)*20 + i%18] = lr1W[i];
    for (int i = tid; i < 63;  i += 256) s_lr2W[(i/9)*12 + i%9]  = lr2W[i];
    if (tid < 9) s_lr1b[tid] = lr1b[tid];
    if (tid < 7) s_lr2b[tid] = lr2b[tid];
    __syncthreads();

    const int half = N * MM;
    const int id = blockIdx.x * 256 + tid;
    if (id >= TT * half) return;
    const int t = id / half;
    const int nm = id - t * half;

    float o18[18];
    load9(o18,     g_lstm[0] + ((size_t)t*half + nm)*12);
    load9(o18 + 9, g_lstm[1] + ((size_t)t*half + nm)*12);

    float q[9];
    #pragma unroll
    for (int d = 0; d < 9; d++) {
        const float* w = s_lr1W + d*20;
        float acc = s_lr1b[d];
        #pragma unroll
        for (int qq = 0; qq < 4; qq++) {
            float4 a = *(const float4*)(w + 4*qq);
            acc = fmaf(a.x, o18[4*qq+0], acc);
            acc = fmaf(a.y, o18[4*qq+1], acc);
            acc = fmaf(a.z, o18[4*qq+2], acc);
            acc = fmaf(a.w, o18[4*qq+3], acc);
        }
        acc = fmaf(w[16], o18[16], acc);
        acc = fmaf(w[17], o18[17], acc);
        q[d] = fmaxf(acc, 0.0f);
    }

    const int n = nm / MM, m = nm - n*MM;
    const int nr0 = numrec[(size_t)n * TT];
    const float vm = (m < nr0) ? 1.0f : 0.0f;
    float* po = out_p + ((size_t)n*(TT*MM) + t*MM + m) * 7;
    #pragma unroll
    for (int k = 0; k < 7; k++)
        po[k] = (s_lr2b[k] + dot9(s_lr2W + k*12, q)) * vm;
}

extern "C" void kernel_launch(void* const* d_in, const int* in_sizes, int n_in,
                              void* d_out, int out_size)
{
    const float* nf    = (const float*)d_in[0];
    const float* pos   = (const float*)d_in[1];
    const float* attm  = (const float*)d_in[2];
    const float* msgW  = (const float*)d_in[3];
    const float* msgb  = (const float*)d_in[4];
    const float* gWih  = (const float*)d_in[5];
    const float* gWhh  = (const float*)d_in[6];
    const float* gbih  = (const float*)d_in[7];
    const float* gbhh  = (const float*)d_in[8];
    const float* ro1W  = (const float*)d_in[9];
    const float* ro1b  = (const float*)d_in[10];
    const float* ro2W  = (const float*)d_in[11];
    const float* ro2b  = (const float*)d_in[12];
    const float* lfWih = (const float*)d_in[13];
    const float* lfWhh = (const float*)d_in[14];
    const float* lfbih = (const float*)d_in[15];
    const float* lfbhh = (const float*)d_in[16];
    const float* lbWih = (const float*)d_in[17];
    const float* lbWhh = (const float*)d_in[18];
    const float* lbbih = (const float*)d_in[19];
    const float* lbbhh = (const float*)d_in[20];
    const float* lr1W  = (const float*)d_in[21];
    const float* lr1b  = (const float*)d_in[22];
    const float* lr2W  = (const float*)d_in[23];
    const float* lr2b  = (const float*)d_in[24];
    const int*   nrec  = (const int*)d_in[25];

    const int N = in_sizes[25] / TT;
    float* out = (float*)d_out;
    float* out_p  = out;                              // pred_label
    float* out_p0 = out + (size_t)N * TT * MM * 7;    // pred_label0

    const int grid1 = (N*TT + 31) / 32;
    const int grid2 = (N*MM*2 + 127) / 128;
    const int grid3 = (N*TT*MM + 255) / 256;

    k1_gru<<<grid1, 192>>>(nf, pos, attm, msgW, msgb, gWih, gWhh, gbih, gbhh,
                           ro1W, ro1b, ro2W, ro2b, nrec, out_p0, N);
    k2_lstm<<<grid2, 128>>>(lfWih, lfWhh, lfbih, lfbhh,
                            lbWih, lbWhh, lbbih, lbbhh, N);
    k3_readout<<<grid3, 256>>>(lr1W, lr1b, lr2W, lr2b, nrec, out_p, N);
}

// round 5
// speedup vs baseline: 1.6372x; 1.1099x over previous
#include <cuda_runtime.h>

#define TT 20
#define MM 6
#define MAXN 8192
typedef unsigned long long u64;

// scratch (allocation-free rule: __device__ globals)
__device__ __align__(16) float g_hidden[(size_t)TT * MAXN * MM * 12];

// ---------------- f32x2 helpers ----------------
__device__ __forceinline__ u64 pk(float a, float b) {
    u64 r; asm("mov.b64 %0, {%1, %2};" : "=l"(r) : "f"(a), "f"(b)); return r;
}
__device__ __forceinline__ void upk(float& a, float& b, u64 v) {
    asm("mov.b64 {%0, %1}, %2;" : "=f"(a), "=f"(b) : "l"(v));
}
__device__ __forceinline__ u64 ffma2(u64 a, u64 b, u64 c) {
    u64 r; asm("fma.rn.f32x2 %0, %1, %2, %3;" : "=l"(r) : "l"(a), "l"(b), "l"(c)); return r;
}

// packed 9-dot: W[0..8] (pairs), v[0..8] (pairs)
__device__ __forceinline__ u64 dotp9(const u64* __restrict__ W, const u64* v, u64 acc) {
    #pragma unroll
    for (int kk = 0; kk < 4; kk++) {
        ulonglong2 w = *(const ulonglong2*)(W + 2*kk);
        acc = ffma2(w.x, v[2*kk],   acc);
        acc = ffma2(w.y, v[2*kk+1], acc);
    }
    acc = ffma2(W[8], v[8], acc);
    return acc;
}
// packed 18-dot: W[0..8] vs va, W[10..18] vs vb (10-offset keeps 16B alignment)
__device__ __forceinline__ u64 dotp18(const u64* __restrict__ W, const u64* va, const u64* vb, u64 acc) {
    acc = dotp9(W, va, acc);
    acc = dotp9(W + 10, vb, acc);
    return acc;
}

// ---------------- MUFU activations ----------------
__device__ __forceinline__ float fsig(float x) {
    float e, r;
    asm("ex2.approx.f32 %0, %1;" : "=f"(e) : "f"(x * -1.4426950408889634f));
    asm("rcp.approx.f32 %0, %1;" : "=f"(r) : "f"(1.0f + e));
    return r;
}
__device__ __forceinline__ float ftanh_(float x) {
    float e, r;
    asm("ex2.approx.f32 %0, %1;" : "=f"(e) : "f"(x * -2.8853900817779268f));
    asm("rcp.approx.f32 %0, %1;" : "=f"(r) : "f"(1.0f + e));
    return fmaf(2.0f, r, -1.0f);
}

// ---------------- scalar dot helpers ----------------
__device__ __forceinline__ float dot9(const float* __restrict__ w, const float* r) {
    float4 a = *(const float4*)w;
    float4 b = *(const float4*)(w + 4);
    float acc = w[8] * r[8];
    acc = fmaf(a.x, r[0], acc); acc = fmaf(a.y, r[1], acc);
    acc = fmaf(a.z, r[2], acc); acc = fmaf(a.w, r[3], acc);
    acc = fmaf(b.x, r[4], acc); acc = fmaf(b.y, r[5], acc);
    acc = fmaf(b.z, r[6], acc); acc = fmaf(b.w, r[7], acc);
    return acc;
}
__device__ __forceinline__ void load9(float* r, const float* __restrict__ p) {
    float4 a = *(const float4*)p;
    float4 b = *(const float4*)(p + 4);
    r[0]=a.x; r[1]=a.y; r[2]=a.z; r[3]=a.w;
    r[4]=b.x; r[5]=b.y; r[6]=b.z; r[7]=b.w;
    r[8]=p[8];
}
__device__ __forceinline__ void store9(float* __restrict__ p, const float* r) {
    *(float4*)p       = make_float4(r[0], r[1], r[2], r[3]);
    *(float4*)(p + 4) = make_float4(r[4], r[5], r[6], r[7]);
    p[8] = r[8];
}

// ================= K1: GRU message passing + p0 readout =================
__global__ __launch_bounds__(192)
void k1_gru(const float* __restrict__ nf, const float* __restrict__ pos,
            const float* __restrict__ attm,
            const float* __restrict__ msgW, const float* __restrict__ msgb,
            const float* __restrict__ gWih, const float* __restrict__ gWhh,
            const float* __restrict__ gbih, const float* __restrict__ gbhh,
            const float* __restrict__ ro1W, const float* __restrict__ ro1b,
            const float* __restrict__ ro2W, const float* __restrict__ ro2b,
            const int* __restrict__ numrec, float* __restrict__ out_p0, int N)
{
    __shared__ __align__(16) u64 s_PM[4][10];     // msg rows (2p,2p+1) packed
    __shared__ __align__(16) u64 s_P1[9][20];     // [0..8] Wih(d,9+d), [10..18] Whh(d,9+d)
    __shared__ __align__(16) u64 s_P3[9][10];     // (Wih[18+d], Whh[18+d]) packed
    __shared__ __align__(16) u64 s_bA[9], s_b3[9], s_bm[4];
    __shared__ __align__(16) float s_msgW8[12], s_ro1W[9*12], s_ro2W[7*12];
    __shared__ __align__(16) float s_ro1b[12], s_ro2b[8];
    __shared__ float s_bm8;
    __shared__ __align__(16) float s_msg[192*12];

    const int tid = threadIdx.x;
    // ---- staging (pre-packed weights) ----
    for (int i = tid; i < 36; i += 192) {
        int p = i/9, k = i%9;
        ((float2*)s_PM)[p*10 + k] = make_float2(msgW[(2*p)*9 + k], msgW[(2*p+1)*9 + k]);
    }
    for (int i = tid; i < 162; i += 192) {
        int d = i/18, k = i%18;
        float lo, hi; int idx;
        if (k < 9) { lo = gWih[d*9+k];        hi = gWih[(9+d)*9+k];        idx = d*20 + k; }
        else { int kk = k-9; lo = gWhh[d*9+kk]; hi = gWhh[(9+d)*9+kk];     idx = d*20 + 10 + kk; }
        ((float2*)s_P1)[idx] = make_float2(lo, hi);
    }
    for (int i = tid; i < 81; i += 192) {
        int d = i/9, k = i%9;
        ((float2*)s_P3)[d*10 + k] = make_float2(gWih[(18+d)*9+k], gWhh[(18+d)*9+k]);
    }
    if (tid < 4) ((float2*)s_bm)[tid] = make_float2(msgb[2*tid], msgb[2*tid+1]);
    if (tid == 4) s_bm8 = msgb[8];
    if (tid < 9) {
        ((float2*)s_bA)[tid] = make_float2(gbih[tid] + gbhh[tid], gbih[9+tid] + gbhh[9+tid]);
        ((float2*)s_b3)[tid] = make_float2(gbih[18+tid], gbhh[18+tid]);
        s_msgW8[tid] = msgW[8*9 + tid];
        s_ro1b[tid] = ro1b[tid];
    }
    for (int i = tid; i < 81; i += 192) s_ro1W[(i/9)*12 + i%9] = ro1W[i];
    for (int i = tid; i < 63; i += 192) s_ro2W[(i/9)*12 + i%9] = ro2W[i];
    if (tid < 7) s_ro2b[tid] = ro2b[tid];

    const int g = tid / 6, m = tid % 6;
    const int ntot = N * TT;
    int nt = blockIdx.x * 32 + g;
    const bool vnt = nt < ntot;
    if (!vnt) nt = 0;
    const int n = nt / TT, t = nt % TT;
    const int nr0 = numrec[(size_t)n * TT];
    const float vm = (m < nr0) ? 1.0f : 0.0f;

    float h[9], attr[6];
    {
        const float* q = nf + (size_t)nt*18 + m*3;
        h[0]=q[0]; h[1]=q[1]; h[2]=q[2];
        const float* pq = pos + (size_t)nt*36 + m*6;
        #pragma unroll
        for (int j = 0; j < 6; j++) h[3+j] = pq[j];
        const float* aq = attm + (size_t)nt*36 + m*6;
        #pragma unroll
        for (int j = 0; j < 6; j++) attr[j] = (j < nr0) ? aq[j] : 0.0f;
    }
    u64 a2[6];
    #pragma unroll
    for (int j = 0; j < 6; j++) a2[j] = pk(attr[j], attr[j]);
    __syncthreads();

    #pragma unroll
    for (int rd = 0; rd < 2; rd++) {
        u64 hd2[9];
        #pragma unroll
        for (int k = 0; k < 9; k++) hd2[k] = pk(h[k], h[k]);
        // msg = W_msg h + b  (4 packed row-pairs + row 8 scalar)
        float msg[9];
        #pragma unroll
        for (int p = 0; p < 4; p++) {
            u64 acc = dotp9(&s_PM[p][0], hd2, s_bm[p]);
            upk(msg[2*p], msg[2*p+1], acc);
        }
        msg[8] = s_bm8 + dot9(s_msgW8, h);
        store9(s_msg + tid*12, msg);
        __syncthreads();
        // mg = sum_j att_j * msg_j   (packed pairs)
        u64 mgp[4] = {0,0,0,0};
        float mg8 = 0.0f;
        #pragma unroll
        for (int j = 0; j < 6; j++) {
            const float* mp = s_msg + (g*6 + j)*12;
            const u64* mpp = (const u64*)mp;
            mgp[0] = ffma2(a2[j], mpp[0], mgp[0]);
            mgp[1] = ffma2(a2[j], mpp[1], mgp[1]);
            mgp[2] = ffma2(a2[j], mpp[2], mgp[2]);
            mgp[3] = ffma2(a2[j], mpp[3], mgp[3]);
            mg8 = fmaf(attr[j], mp[8], mg8);
        }
        float mg[9];
        #pragma unroll
        for (int p = 0; p < 4; p++) upk(mg[2*p], mg[2*p+1], mgp[p]);
        mg[8] = mg8;
        u64 mg2[9], mh2[9];
        #pragma unroll
        for (int k = 0; k < 9; k++) { mg2[k] = pk(mg[k], mg[k]); mh2[k] = pk(mg[k], h[k]); }
        // GRU cell
        float hn[9];
        #pragma unroll
        for (int d = 0; d < 9; d++) {
            u64 acc1 = dotp18(&s_P1[d][0], mg2, hd2, s_bA[d]);   // (r_pre, z_pre)
            u64 acc3 = dotp9(&s_P3[d][0], mh2, s_b3[d]);         // (gx2, gh2)
            float a0, a1, gx2, gh2;
            upk(a0, a1, acc1);
            upk(gx2, gh2, acc3);
            float r  = fsig(a0);
            float z  = fsig(a1);
            float nn = ftanh_(fmaf(r, gh2, gx2));
            hn[d] = fmaf(z, h[d] - nn, nn) * vm;
        }
        #pragma unroll
        for (int d = 0; d < 9; d++) h[d] = hn[d];
        __syncthreads();
    }

    if (vnt) {
        store9(g_hidden + ((size_t)t * (N*MM) + n*MM + m) * 12, h);
        float q[9];
        #pragma unroll
        for (int d = 0; d < 9; d++)
            q[d] = fmaxf(s_ro1b[d] + dot9(s_ro1W + d*12, h), 0.0f);
        float* po = out_p0 + ((size_t)n*(TT*MM) + t*MM + m) * 7;
        #pragma unroll
        for (int k = 0; k < 7; k++)
            po[k] = (s_ro2b[k] + dot9(s_ro2W + k*12, q)) * vm;
    }
}

// ================= K2f: fused Bi-LSTM + final readout =================
// block = 64 nm x 2 dirs = 128 threads. Phase 1: each thread runs one chain,
// h-sequence cached in smem (stride 181 floats, conflict-free). Phase 2:
// cooperative readout of 20x64 (t,nm) outputs from smem.
#define K2_NM 64
#define K2_THREADS 128
#define HSTRIDE 181

__global__ __launch_bounds__(K2_THREADS)
void k2_fused(const float* __restrict__ lfWih, const float* __restrict__ lfWhh,
              const float* __restrict__ lfbih, const float* __restrict__ lfbhh,
              const float* __restrict__ lbWih, const float* __restrict__ lbWhh,
              const float* __restrict__ lbbih, const float* __restrict__ lbbhh,
              const float* __restrict__ lr1W, const float* __restrict__ lr1b,
              const float* __restrict__ lr2W, const float* __restrict__ lr2b,
              const int* __restrict__ numrec, float* __restrict__ out_p, int N)
{
    extern __shared__ __align__(16) float s_h[];   // K2_THREADS * HSTRIDE floats

    __shared__ __align__(16) u64 s_WA[2][9][20];   // gates (i,f): [0..8] Wi, [10..18] Wh
    __shared__ __align__(16) u64 s_WB[2][9][20];   // gates (g,o)
    __shared__ __align__(16) u64 s_bA2[18], s_bB2[18];
    __shared__ __align__(16) u64 s_R1[4][20];      // lr1 row pairs (2p,2p+1), 18 cols
    __shared__ __align__(16) u64 s_R1b[4];
    __shared__ __align__(16) u64 s_R2[3][10];      // lr2 row pairs, 9 cols
    __shared__ __align__(16) u64 s_R2b[3];
    __shared__ __align__(16) float s_R1s[20], s_R2s[12];  // scalar rows 8 / 6
    __shared__ float s_R1bs, s_R2bs;

    const int tid = threadIdx.x;
    // ---- weight staging ----
    for (int i = tid; i < 324; i += K2_THREADS) {
        int dirn = i / 162, r = i % 162, d = r/18, k = r%18;
        const float* Wi = dirn ? lbWih : lfWih;
        const float* Wh = dirn ? lbWhh : lfWhh;
        float loA, hiA, loB, hiB; int idx;
        if (k < 9) {
            loA = Wi[d*9+k];      hiA = Wi[(9+d)*9+k];
            loB = Wi[(18+d)*9+k]; hiB = Wi[(27+d)*9+k];
            idx = k;
        } else {
            int kk = k - 9;
            loA = Wh[d*9+kk];      hiA = Wh[(9+d)*9+kk];
            loB = Wh[(18+d)*9+kk]; hiB = Wh[(27+d)*9+kk];
            idx = 10 + kk;
        }
        ((float2*)&s_WA[dirn][d][0])[idx] = make_float2(loA, hiA);
        ((float2*)&s_WB[dirn][d][0])[idx] = make_float2(loB, hiB);
    }
    if (tid < 18) {
        int dirn = tid / 9, d = tid % 9;
        const float* bi = dirn ? lbbih : lfbih;
        const float* bh = dirn ? lbbhh : lfbhh;
        ((float2*)s_bA2)[tid] = make_float2(bi[d] + bh[d],       bi[9+d] + bh[9+d]);
        ((float2*)s_bB2)[tid] = make_float2(bi[18+d] + bh[18+d], bi[27+d] + bh[27+d]);
    }
    for (int i = tid; i < 72; i += K2_THREADS) {
        int p = i/18, k = i%18;
        ((float2*)&s_R1[p][0])[k] = make_float2(lr1W[(2*p)*18+k], lr1W[(2*p+1)*18+k]);
    }
    if (tid < 18) s_R1s[tid] = lr1W[8*18 + tid];
    for (int i = tid; i < 27; i += K2_THREADS) {
        int p = i/9, k = i%9;
        ((float2*)&s_R2[p][0])[k] = make_float2(lr2W[(2*p)*9+k], lr2W[(2*p+1)*9+k]);
    }
    if (tid < 9) s_R2s[tid] = lr2W[6*9 + tid];
    if (tid < 4) ((float2*)s_R1b)[tid] = make_float2(lr1b[2*tid], lr1b[2*tid+1]);
    if (tid == 4) s_R1bs = lr1b[8];
    if (tid < 3) ((float2*)s_R2b)[tid] = make_float2(lr2b[2*tid], lr2b[2*tid+1]);
    if (tid == 3) s_R2bs = lr2b[6];
    __syncthreads();

    const int half = N * MM;
    const int nml  = tid & (K2_NM - 1);
    const int dirn = tid >> 6;                  // warp-uniform
    const int nm0  = blockIdx.x * K2_NM + nml;

    // ---- phase 1: run this thread's chain, caching h(t) in smem ----
    if (nm0 < half) {
        const u64* WA = &s_WA[dirn][0][0];
        const u64* WB = &s_WB[dirn][0][0];
        const u64* bA = s_bA2 + dirn*9;
        const u64* bB = s_bB2 + dirn*9;
        float* myh = s_h + tid * HSTRIDE;

        float h[9], c[9];
        #pragma unroll
        for (int d = 0; d < 9; d++) { h[d] = 0.0f; c[d] = 0.0f; }

        const long tstep = (long)half * 12;
        const long sstep = dirn ? -tstep : tstep;
        const float* xp = g_hidden + (size_t)nm0*12 + (dirn ? (size_t)(TT-1)*tstep : 0);

        float x[9];
        load9(x, xp);
        for (int s = 0; s < TT; s++) {
            xp += sstep;
            float xn[9];
            if (s < TT-1) load9(xn, xp);        // prefetch next step's input
            u64 xx[9], hh[9];
            #pragma unroll
            for (int k = 0; k < 9; k++) { xx[k] = pk(x[k], x[k]); hh[k] = pk(h[k], h[k]); }
            #pragma unroll
            for (int d = 0; d < 9; d++) {
                u64 accA = dotp18(WA + d*20, xx, hh, bA[d]);   // (i_pre, f_pre)
                u64 accB = dotp18(WB + d*20, xx, hh, bB[d]);   // (g_pre, o_pre)
                float gi, gf, gG, go;
                upk(gi, gf, accA);
                upk(gG, go, accB);
                float i_ = fsig(gi);
                float f_ = fsig(gf);
                float gg = ftanh_(gG);
                float o_ = fsig(go);
                c[d] = fmaf(f_, c[d], i_ * gg);
                h[d] = o_ * ftanh_(c[d]);
            }
            const int t = dirn ? (TT-1-s) : s;
            #pragma unroll
            for (int d = 0; d < 9; d++) myh[t*9 + d] = h[d];
            #pragma unroll
            for (int d = 0; d < 9; d++) x[d] = xn[d];
        }
    }
    __syncthreads();

    // ---- phase 2: cooperative readout over 20*64 (t,nm) tasks ----
    for (int r = tid; r < TT * K2_NM; r += K2_THREADS) {
        const int t   = r >> 6;
        const int lnm = r & (K2_NM - 1);
        const int nm  = blockIdx.x * K2_NM + lnm;
        if (nm >= half) continue;

        const float* hf = s_h + lnm * HSTRIDE + t*9;
        const float* hb = s_h + (K2_NM + lnm) * HSTRIDE + t*9;
        float o18[18];
        #pragma unroll
        for (int k = 0; k < 9; k++) { o18[k] = hf[k]; o18[9+k] = hb[k]; }
        u64 o2[18];
        #pragma unroll
        for (int k = 0; k < 18; k++) o2[k] = pk(o18[k], o18[k]);

        float q[9];
        #pragma unroll
        for (int p = 0; p < 4; p++) {
            u64 acc = s_R1b[p];
            #pragma unroll
            for (int k = 0; k < 18; k++) acc = ffma2(s_R1[p][k], o2[k], acc);
            float a, b; upk(a, b, acc);
            q[2*p]   = fmaxf(a, 0.0f);
            q[2*p+1] = fmaxf(b, 0.0f);
        }
        {
            float acc = s_R1bs;
            #pragma unroll
            for (int k = 0; k < 18; k++) acc = fmaf(s_R1s[k], o18[k], acc);
            q[8] = fmaxf(acc, 0.0f);
        }
        u64 q2[9];
        #pragma unroll
        for (int k = 0; k < 9; k++) q2[k] = pk(q[k], q[k]);

        float o7[7];
        #pragma unroll
        for (int p = 0; p < 3; p++) {
            u64 acc = s_R2b[p];
            #pragma unroll
            for (int k = 0; k < 9; k++) acc = ffma2(s_R2[p][k], q2[k], acc);
            upk(o7[2*p], o7[2*p+1], acc);
        }
        {
            float acc = s_R2bs;
            #pragma unroll
            for (int k = 0; k < 9; k++) acc = fmaf(s_R2s[k], q[k], acc);
            o7[6] = acc;
        }

        const int n = nm / MM, m = nm - n*MM;
        const int nr0 = numrec[(size_t)n * TT];
        const float vm = (m < nr0) ? 1.0f : 0.0f;
        float* po = out_p + ((size_t)n*(TT*MM) + t*MM + m) * 7;
        #pragma unroll
        for (int k = 0; k < 7; k++) po[k] = o7[k] * vm;
    }
}

extern "C" void kernel_launch(void* const* d_in, const int* in_sizes, int n_in,
                              void* d_out, int out_size)
{
    const float* nf    = (const float*)d_in[0];
    const float* pos   = (const float*)d_in[1];
    const float* attm  = (const float*)d_in[2];
    const float* msgW  = (const float*)d_in[3];
    const float* msgb  = (const float*)d_in[4];
    const float* gWih  = (const float*)d_in[5];
    const float* gWhh  = (const float*)d_in[6];
    const float* gbih  = (const float*)d_in[7];
    const float* gbhh  = (const float*)d_in[8];
    const float* ro1W  = (const float*)d_in[9];
    const float* ro1b  = (const float*)d_in[10];
    const float* ro2W  = (const float*)d_in[11];
    const float* ro2b  = (const float*)d_in[12];
    const float* lfWih = (const float*)d_in[13];
    const float* lfWhh = (const float*)d_in[14];
    const float* lfbih = (const float*)d_in[15];
    const float* lfbhh = (const float*)d_in[16];
    const float* lbWih = (const float*)d_in[17];
    const float* lbWhh = (const float*)d_in[18];
    const float* lbbih = (const float*)d_in[19];
    const float* lbbhh = (const float*)d_in[20];
    const float* lr1W  = (const float*)d_in[21];
    const float* lr1b  = (const float*)d_in[22];
    const float* lr2W  = (const float*)d_in[23];
    const float* lr2b  = (const float*)d_in[24];
    const int*   nrec  = (const int*)d_in[25];

    const int N = in_sizes[25] / TT;
    float* out = (float*)d_out;
    float* out_p  = out;                              // pred_label
    float* out_p0 = out + (size_t)N * TT * MM * 7;    // pred_label0

    const int grid1 = (N*TT + 31) / 32;
    const int grid2 = (N*MM + K2_NM - 1) / K2_NM;
    const int smem2 = K2_THREADS * HSTRIDE * sizeof(float);   // 92672 B

    cudaFuncSetAttribute(k2_fused, cudaFuncAttributeMaxDynamicSharedMemorySize, smem2);

    k1_gru<<<grid1, 192>>>(nf, pos, attm, msgW, msgb, gWih, gWhh, gbih, gbhh,
                           ro1W, ro1b, ro2W, ro2b, nrec, out_p0, N);
    k2_fused<<<grid2, K2_THREADS, smem2>>>(lfWih, lfWhh, lfbih, lfbhh,
                                           lbWih, lbWhh, lbbih, lbbhh,
                                           lr1W, lr1b, lr2W, lr2b, nrec, out_p, N);
}